// round 15
// baseline (speedup 1.0000x reference)
#include <cuda_runtime.h>
#include <cuda_fp16.h>

typedef unsigned long long ull;
typedef unsigned int u32;

// ================= common helpers =================
__device__ __forceinline__ u32 smem_to_u32(const void* p) {
    u32 a; asm("{ .reg .u64 t; cvta.to.shared.u64 t, %1; cvt.u32.u64 %0, t; }" : "=r"(a) : "l"(p));
    return a;
}
__device__ __forceinline__ float ex2f(float x) {
    float y; asm("ex2.approx.f32 %0, %1;" : "=f"(y) : "f"(x)); return y;
}
#define CP_ASYNC16(dst, src) asm volatile("cp.async.cg.shared.global [%0], [%1], 16;" :: "r"(dst), "l"(src) : "memory")
#define CP_COMMIT()          asm volatile("cp.async.commit_group;" ::: "memory")
#define CP_WAIT0()           asm volatile("cp.async.wait_group 0;" ::: "memory")
#define CP_WAIT1()           asm volatile("cp.async.wait_group 1;" ::: "memory")

#define LDMX4(r, addr) \
    asm volatile("ldmatrix.sync.aligned.m8n8.x4.shared.b16 {%0,%1,%2,%3}, [%4];" \
        : "=r"((r)[0]), "=r"((r)[1]), "=r"((r)[2]), "=r"((r)[3]) : "r"(addr))
#define LDMX4T(r, addr) \
    asm volatile("ldmatrix.sync.aligned.m8n8.x4.trans.shared.b16 {%0,%1,%2,%3}, [%4];" \
        : "=r"((r)[0]), "=r"((r)[1]), "=r"((r)[2]), "=r"((r)[3]) : "r"(addr))

__device__ __forceinline__ void mma16816(float* c, const u32* a, u32 b0, u32 b1) {
    asm volatile("mma.sync.aligned.m16n8k16.row.col.f32.f16.f16.f32 "
        "{%0,%1,%2,%3}, {%4,%5,%6,%7}, {%8,%9}, {%0,%1,%2,%3};"
        : "+f"(c[0]), "+f"(c[1]), "+f"(c[2]), "+f"(c[3])
        : "r"(a[0]), "r"(a[1]), "r"(a[2]), "r"(a[3]), "r"(b0), "r"(b1));
}

// ================= global scratch =================
__device__ __align__(256) __half g_as[3][2][4194304];  // input splits [mat][split][m*1024+k]
__device__ __align__(256) __half g_bs[4][2][1048576];  // weight splits [mat][split][n*1024+k]
__device__ __align__(256) __half g_qs[2][4194304];     // qh 2-split (prescaled 0.125*log2e)
__device__ __align__(256) __half g_ks[2][4194304];     // kh 2-split
__device__ __align__(256) __half g_vs[4194304];        // vh single fp16
__device__ __align__(256) __half g_cs[4194304];        // ctx single fp16

__constant__ int c_pa[3] = { 0, 0, 1 };
__constant__ int c_pb[3] = { 0, 1, 0 };

// ================= split helpers (fp16 h+l) =================
__device__ __forceinline__ u32 pk2h(__half a, __half b) {
    __half2 t = __halves2half2(a, b);
    return *reinterpret_cast<u32*>(&t);
}
__device__ __forceinline__ void split2h(float x, __half& h, __half& l) {
    h = __float2half_rn(x);
    l = __float2half_rn(x - __half2float(h));
}
__device__ __forceinline__ void split2pkh(float x, float y, u32& hi, u32& lo) {
    __half hx, lx, hy, ly;
    split2h(x, hx, lx); split2h(y, hy, ly);
    hi = pk2h(hx, hy); lo = pk2h(lx, ly);
}

// ================= merged split kernel ==================
// [0,12288): q/k/v inputs; [12288,13312): Wo (h only); [13312,13696): Wq/Wk/Wv transpose
__global__ void split_all_kernel(const float* __restrict__ q, const float* __restrict__ k,
                                 const float* __restrict__ v,
                                 const float* __restrict__ Wq, const float* __restrict__ Wk,
                                 const float* __restrict__ Wv, const float* __restrict__ Wo) {
    __shared__ float ts[128 * 65];
    u32 bid = blockIdx.x;
    const int tid = threadIdx.x;
    if (bid < 12288u) {
        int y = bid / 4096u;
        u32 idx = (bid % 4096u) * 256u + (u32)tid;
        const float* in = (y == 0) ? q : (y == 1) ? k : v;
        float4 x = ((const float4*)in)[idx];
        u32 o = idx * 4u;
        if (y < 2) {
            u32 h01, l01, h23, l23;
            split2pkh(x.x, x.y, h01, l01);
            split2pkh(x.z, x.w, h23, l23);
            *(uint2*)&g_as[y][0][o] = make_uint2(h01, h23);
            *(uint2*)&g_as[y][1][o] = make_uint2(l01, l23);
        } else {
            *(uint2*)&g_as[2][0][o] = make_uint2(
                pk2h(__float2half_rn(x.x), __float2half_rn(x.y)),
                pk2h(__float2half_rn(x.z), __float2half_rn(x.w)));
        }
    } else if (bid < 13312u) {
        u32 idx = (bid - 12288u) * 256u + (u32)tid;
        float4 x = ((const float4*)Wo)[idx];
        u32 o = idx * 4u;
        *(uint2*)&g_bs[3][0][o] = make_uint2(
            pk2h(__float2half_rn(x.x), __float2half_rn(x.y)),
            pk2h(__float2half_rn(x.z), __float2half_rn(x.w)));
    } else {
        u32 bid2 = bid - 13312u;
        u32 mat = bid2 >> 7, r = bid2 & 127u;
        u32 h = r >> 3, dt = r & 7u;
        const float* W = (mat == 0) ? Wq : (mat == 1) ? Wk : Wv;
        const u32 d0 = dt * 128u;

        u32 kk = (u32)tid & 63u, dl = (u32)tid >> 6;
#pragma unroll
        for (int it = 0; it < 32; it++) {
            u32 d = dl + (u32)it * 4u;
            ts[d * 65u + kk] = W[h * 65536u + (d0 + d) * 64u + kk];
        }
        __syncthreads();

        u32 kk2 = (u32)tid >> 6, dc = ((u32)tid & 63u) * 2u;
#pragma unroll
        for (int it = 0; it < 16; it++) {
            u32 kkr = kk2 + (u32)it * 4u;
            float x0 = ts[dc * 65u + kkr];
            float x1 = ts[(dc + 1u) * 65u + kkr];
            u32 o = (h * 64u + kkr) * 1024u + d0 + dc;
            if (mat < 2u) {
                u32 hi, lo;
                split2pkh(x0, x1, hi, lo);
                *(u32*)&g_bs[mat][0][o] = hi;
                *(u32*)&g_bs[mat][1][o] = lo;
            } else {
                *(u32*)&g_bs[2][0][o] = pk2h(__float2half_rn(x0), __float2half_rn(x1));
            }
        }
    }
}

// ================= mma.sync split-fp32 GEMM (8 warps, 64x32 warp tile) ========
// mats 0,1: 3 products. mat 2: 1 product. mat 3 (outproj): 1 product.
#define GPITCH 144u
#define GTILE  18432u        // 128 * 144
#define GSTAGE 36864u        // A + B
#define GSMEM  110592u       // 3 stages
#define BSPLIT 2097152ull

__device__ __forceinline__ void gemm_issue(const char* aB, const char* bB, ull asplit,
                                           u32 base, int v, int s, u32 bm, u32 bn, int tid) {
    int p = v >> 4;
    u32 kb = (u32)(v & 15) * 128u;
    const char* srcA = aB + (ull)c_pa[p] * asplit + kb;
    const char* srcB = bB + (ull)c_pb[p] * BSPLIT + kb;
    u32 stA = base + (u32)s * GSTAGE;
    u32 stB = stA + GTILE;
#pragma unroll
    for (int j = 0; j < 4; j++) {
        u32 c = (u32)tid + (u32)j * 256u;
        u32 row = c >> 3, ch = (c & 7u) << 4;
        CP_ASYNC16(stA + row * GPITCH + ch, srcA + (ull)(bm + row) * 2048ull + ch);
        CP_ASYNC16(stB + row * GPITCH + ch, srcB + (ull)(bn + row) * 2048ull + ch);
    }
    CP_COMMIT();
}

__global__ void __launch_bounds__(256) gemm_mma_kernel(int mat_base, float* Cout,
                                                       const float* __restrict__ bias) {
    extern __shared__ char sm_g[];
    u32 base = smem_to_u32(sm_g);
    const int tid = threadIdx.x, lane = tid & 31, wid = tid >> 5;
    const u32 bm = blockIdx.y << 7, bn = blockIdx.x << 7;
    const int wm = (wid >> 2) << 6, wn = (wid & 3) << 5;
    const int mat = mat_base + blockIdx.z;

    const char* aB; const char* bB; ull asplit;
    if (mat < 3) { aB = (const char*)g_as[mat][0]; bB = (const char*)g_bs[mat][0]; asplit = 8388608ull; }
    else         { aB = (const char*)g_cs;         bB = (const char*)g_bs[3][0];   asplit = 0ull; }

    float acc[4][4][4];
#pragma unroll
    for (int mi = 0; mi < 4; mi++)
#pragma unroll
        for (int ni = 0; ni < 4; ni++)
#pragma unroll
            for (int e = 0; e < 4; e++) acc[mi][ni][e] = 0.f;

    const int NV = (mat >= 2) ? 16 : 48;
    gemm_issue(aB, bB, asplit, base, 0, 0, bm, bn, tid);
    gemm_issue(aB, bB, asplit, base, 1, 1, bm, bn, tid);

    int s = 0;
    for (int v = 0; v < NV; v++) {
        if (v == NV - 1) { CP_WAIT0(); } else { CP_WAIT1(); }
        __syncthreads();
        if (v + 2 < NV) {
            int s2 = (s + 2 >= 3) ? s - 1 : s + 2;
            gemm_issue(aB, bB, asplit, base, v + 2, s2, bm, bn, tid);
        }

        u32 stA = base + (u32)s * GSTAGE;
        u32 stB = stA + GTILE;
        u32 lrow = (u32)(lane & 15) * GPITCH + (u32)(lane >> 4) * 16u;
#pragma unroll
        for (int ks = 0; ks < 4; ks++) {
            u32 a[4][4], b[2][4];
            u32 abase = stA + (u32)wm * GPITCH + lrow + (u32)ks * 32u;
            u32 bbase = stB + (u32)wn * GPITCH + lrow + (u32)ks * 32u;
#pragma unroll
            for (int mi = 0; mi < 4; mi++) LDMX4(a[mi], abase + (u32)mi * (16u * GPITCH));
#pragma unroll
            for (int nj = 0; nj < 2; nj++) LDMX4(b[nj], bbase + (u32)nj * (16u * GPITCH));
#pragma unroll
            for (int mi = 0; mi < 4; mi++)
#pragma unroll
                for (int ni = 0; ni < 4; ni++)
                    mma16816(acc[mi][ni], a[mi], b[ni >> 1][ni & 1], b[ni >> 1][(ni & 1) + 2]);
        }
        s = (s + 1 == 3) ? 0 : s + 1;
    }

    // q-heads prescaled by (1/8)*log2(e) so attention can use raw ex2
    const float pre = (mat == 0) ? 0.18033688f : 1.0f;
#pragma unroll
    for (int mi = 0; mi < 4; mi++)
#pragma unroll
        for (int ni = 0; ni < 4; ni++) {
            u32 r0 = bm + (u32)wm + (u32)mi * 16u + (u32)(lane >> 2);
            u32 col = bn + (u32)wn + (u32)ni * 8u + (u32)((lane & 3) << 1);
            float v0 = acc[mi][ni][0] * pre, v1 = acc[mi][ni][1] * pre;
            float v2 = acc[mi][ni][2] * pre, v3 = acc[mi][ni][3] * pre;
            if (mat == 3) {
                float b0 = bias[col], b1 = bias[col + 1];
                *(float2*)&Cout[(ull)r0 * 1024ull + col] = make_float2(v0 + b0, v1 + b1);
                *(float2*)&Cout[(ull)(r0 + 8) * 1024ull + col] = make_float2(v2 + b0, v3 + b1);
            } else if (mat == 2) {
                *(u32*)&g_vs[r0 * 1024u + col] =
                    pk2h(__float2half_rn(v0), __float2half_rn(v1));
                *(u32*)&g_vs[(r0 + 8) * 1024u + col] =
                    pk2h(__float2half_rn(v2), __float2half_rn(v3));
            } else {
                __half* d0 = (mat == 0) ? g_qs[0] : g_ks[0];
                __half* d1 = (mat == 0) ? g_qs[1] : g_ks[1];
                u32 h01, l01, h23, l23;
                split2pkh(v0, v1, h01, l01); split2pkh(v2, v3, h23, l23);
                *(u32*)&d0[r0 * 1024u + col] = h01;
                *(u32*)&d1[r0 * 1024u + col] = l01;
                *(u32*)&d0[(r0 + 8) * 1024u + col] = h23;
                *(u32*)&d1[(r0 + 8) * 1024u + col] = l23;
            }
        }
}

// ================= mma.sync flash attention (base-2 softmax) =================
// QK^T: 3 products (hh, hl, lh); PV: 1 product (P fp16 unsplit, V single fp16).
#define AP   144u
#define QSZ  18432u     // 128*144 per split
#define KSZ  9216u      // 64*144 per split
#define ASTAGE 27648u   // 2 K splits + 1 V
#define ASMEM  92160u   // 2*QSZ + 2*ASTAGE

__device__ __forceinline__ void attn_issue(u32 base, int s, int key0, u32 hb, int tid) {
    u32 st = base + 2u * QSZ + (u32)s * ASTAGE;
#pragma unroll
    for (int i = 0; i < 6; i++) {
        u32 u = (u32)tid + (u32)i * 256u;
        if (u < 1024u) {
            u32 sp = u >> 9, r = (u >> 3) & 63u, ch = (u & 7u) << 4;
            const char* src = (const char*)g_ks[sp] + (ull)(key0 + (int)r) * 2048ull + hb + ch;
            CP_ASYNC16(st + sp * KSZ + r * AP + ch, src);
        } else {
            u32 u2 = u - 1024u;
            u32 r = u2 >> 3, ch = (u2 & 7u) << 4;
            const char* src = (const char*)g_vs + (ull)(key0 + (int)r) * 2048ull + hb + ch;
            CP_ASYNC16(st + 2u * KSZ + r * AP + ch, src);
        }
    }
    CP_COMMIT();
}

__global__ void __launch_bounds__(256, 2) attn_mma_kernel() {
    extern __shared__ char sma[];
    u32 base = smem_to_u32(sma);
    const int tid = threadIdx.x, lane = tid & 31, w = tid >> 5;
    const int b = blockIdx.y >> 4, h = blockIdx.y & 15;
    const u32 hb = (u32)h * 128u;
    const int m0 = b * 2048 + (blockIdx.x << 7);
    const int kv0 = b * 2048;

#pragma unroll
    for (int i = 0; i < 8; i++) {
        u32 u = (u32)tid + (u32)i * 256u;
        u32 sp = u >> 10, r = (u >> 3) & 127u, ch = (u & 7u) << 4;
        const char* src = (const char*)g_qs[sp] + (ull)(m0 + (int)r) * 2048ull + hb + ch;
        CP_ASYNC16(base + sp * QSZ + r * AP + ch, src);
    }
    CP_COMMIT();
    attn_issue(base, 0, kv0, hb, tid);

    float o[8][4];
#pragma unroll
    for (int i = 0; i < 8; i++)
#pragma unroll
        for (int e = 0; e < 4; e++) o[i][e] = 0.f;
    float mg0 = -1e30f, mg1 = -1e30f, l0 = 0.f, l1 = 0.f;

    const u32 lrow = (u32)(lane & 15) * AP + (u32)(lane >> 4) * 16u;
    const u32 qbase = base + (u32)w * (16u * AP) + lrow;

    for (int c = 0; c < 32; c++) {
        if (c + 1 < 32) { attn_issue(base, (c + 1) & 1, kv0 + (c + 1) * 64, hb, tid); CP_WAIT1(); }
        else            { CP_WAIT0(); }
        __syncthreads();

        u32 stK = base + 2u * QSZ + (u32)(c & 1) * ASTAGE;
        u32 stV = stK + 2u * KSZ;

        // ---- S = QK^T (3 products: hh, hl, lh); scores already in log2 domain ----
        float sv[8][4];
#pragma unroll
        for (int i = 0; i < 8; i++)
#pragma unroll
            for (int e = 0; e < 4; e++) sv[i][e] = 0.f;

#pragma unroll
        for (int ks = 0; ks < 4; ks++) {
            u32 aq[2][4];
#pragma unroll
            for (int sp = 0; sp < 2; sp++) LDMX4(aq[sp], qbase + sp * QSZ + (u32)ks * 32u);
#pragma unroll
            for (int sb = 0; sb < 2; sb++) {
                u32 bf[4][4];
                u32 bb = stK + (u32)sb * KSZ + lrow + (u32)ks * 32u;
#pragma unroll
                for (int q = 0; q < 4; q++) LDMX4(bf[q], bb + (u32)q * (16u * AP));
                const int na = (sb == 0) ? 2 : 1;   // hh, lh | hl
#pragma unroll
                for (int ai = 0; ai < 2; ai++) {
                    if (ai < na) {
#pragma unroll
                        for (int q = 0; q < 4; q++) {
                            mma16816(sv[2 * q],     aq[ai], bf[q][0], bf[q][2]);
                            mma16816(sv[2 * q + 1], aq[ai], bf[q][1], bf[q][3]);
                        }
                    }
                }
            }
        }

        // ---- online softmax (base 2) ----
        float cm0 = -1e30f, cm1 = -1e30f;
#pragma unroll
        for (int i = 0; i < 8; i++) {
            cm0 = fmaxf(cm0, fmaxf(sv[i][0], sv[i][1]));
            cm1 = fmaxf(cm1, fmaxf(sv[i][2], sv[i][3]));
        }
        cm0 = fmaxf(cm0, __shfl_xor_sync(0xffffffffu, cm0, 1));
        cm0 = fmaxf(cm0, __shfl_xor_sync(0xffffffffu, cm0, 2));
        cm1 = fmaxf(cm1, __shfl_xor_sync(0xffffffffu, cm1, 1));
        cm1 = fmaxf(cm1, __shfl_xor_sync(0xffffffffu, cm1, 2));
        float nm0 = fmaxf(mg0, cm0), nm1 = fmaxf(mg1, cm1);
        bool rescale = (nm0 > mg0) || (nm1 > mg1);
        float corr0 = ex2f(mg0 - nm0), corr1 = ex2f(mg1 - nm1);
        float rs0 = 0.f, rs1 = 0.f;
#pragma unroll
        for (int i = 0; i < 8; i++) {
            sv[i][0] = ex2f(sv[i][0] - nm0);
            sv[i][1] = ex2f(sv[i][1] - nm0);
            sv[i][2] = ex2f(sv[i][2] - nm1);
            sv[i][3] = ex2f(sv[i][3] - nm1);
            rs0 += sv[i][0] + sv[i][1];
            rs1 += sv[i][2] + sv[i][3];
        }
        rs0 += __shfl_xor_sync(0xffffffffu, rs0, 1);
        rs0 += __shfl_xor_sync(0xffffffffu, rs0, 2);
        rs1 += __shfl_xor_sync(0xffffffffu, rs1, 1);
        rs1 += __shfl_xor_sync(0xffffffffu, rs1, 2);
        l0 = l0 * corr0 + rs0; l1 = l1 * corr1 + rs1;
        mg0 = nm0; mg1 = nm1;
        if (__any_sync(0xffffffffu, rescale)) {
#pragma unroll
            for (int i = 0; i < 8; i++) {
                o[i][0] *= corr0; o[i][1] *= corr0;
                o[i][2] *= corr1; o[i][3] *= corr1;
            }
        }

        // ---- P -> fp16 A-fragments (unsplit) ----
        u32 ph[4][4];
#pragma unroll
        for (int j = 0; j < 4; j++) {
            ph[j][0] = pk2h(__float2half_rn(sv[2 * j][0]),     __float2half_rn(sv[2 * j][1]));
            ph[j][1] = pk2h(__float2half_rn(sv[2 * j][2]),     __float2half_rn(sv[2 * j][3]));
            ph[j][2] = pk2h(__float2half_rn(sv[2 * j + 1][0]), __float2half_rn(sv[2 * j + 1][1]));
            ph[j][3] = pk2h(__float2half_rn(sv[2 * j + 1][2]), __float2half_rn(sv[2 * j + 1][3]));
        }

        // ---- O += P V (1 product; V single fp16 via ldmatrix.trans) ----
#pragma unroll
        for (int j = 0; j < 4; j++) {
            u32 vrow = stV + (16u * (u32)j + (u32)(lane & 7) + (u32)((lane >> 4) << 3)) * AP
                       + (u32)(((lane >> 3) & 1) << 4);
            u32 bv[4][4];
#pragma unroll
            for (int q = 0; q < 4; q++) LDMX4T(bv[q], vrow + (u32)q * 32u);
#pragma unroll
            for (int q = 0; q < 4; q++) {
                mma16816(o[2 * q],     ph[j], bv[q][0], bv[q][2]);
                mma16816(o[2 * q + 1], ph[j], bv[q][1], bv[q][3]);
            }
        }
        __syncthreads();
    }

    float inv0 = 1.0f / l0, inv1 = 1.0f / l1;
    u32 r0 = (u32)m0 + (u32)w * 16u + (u32)(lane >> 2);
    u32 cb = (u32)h * 64u + (u32)((lane & 3) << 1);
#pragma unroll
    for (int i = 0; i < 8; i++) {
        u32 col = cb + (u32)i * 8u;
        *(u32*)&g_cs[r0 * 1024u + col] =
            pk2h(__float2half_rn(o[i][0] * inv0), __float2half_rn(o[i][1] * inv0));
        *(u32*)&g_cs[(r0 + 8u) * 1024u + col] =
            pk2h(__float2half_rn(o[i][2] * inv1), __float2half_rn(o[i][3] * inv1));
    }
}

// ================= launch =================
extern "C" void kernel_launch(void* const* d_in, const int* in_sizes, int n_in,
                              void* d_out, int out_size) {
    const float* q  = (const float*)d_in[0];
    const float* k  = (const float*)d_in[1];
    const float* v  = (const float*)d_in[2];
    const float* Wq = (const float*)d_in[3];
    const float* Wk = (const float*)d_in[4];
    const float* Wv = (const float*)d_in[5];
    const float* Wo = (const float*)d_in[6];
    const float* bo = (const float*)d_in[7];
    float* out = (float*)d_out;

    split_all_kernel<<<13696, 256>>>(q, k, v, Wq, Wk, Wv, Wo);

    cudaFuncSetAttribute(gemm_mma_kernel, cudaFuncAttributeMaxDynamicSharedMemorySize, GSMEM);
    gemm_mma_kernel<<<dim3(8, 32, 3), 256, GSMEM>>>(0, nullptr, nullptr);

    cudaFuncSetAttribute(attn_mma_kernel, cudaFuncAttributeMaxDynamicSharedMemorySize, ASMEM);
    attn_mma_kernel<<<dim3(16, 32), 256, ASMEM>>>();

    gemm_mma_kernel<<<dim3(8, 32, 1), 256, GSMEM>>>(3, out, bo);
}